// round 6
// baseline (speedup 1.0000x reference)
#include <cuda_runtime.h>
#include <math.h>

// Problem dims
#define NR   512
#define DM   512
#define NH   8
#define HE   64
#define FF   2048
#define NL   6
#define MIX3 768

// ---------------- scratch (device globals; no allocation) ----------------
__device__ float g_h[NR * DM];
__device__ float g_q[NR * DM];
__device__ float g_k[NR * DM];
__device__ float g_v[NR * DM];
__device__ float g_attn[NR * DM];
__device__ float g_ffn[NR * FF];
__device__ float g_part[8 * NR * DM];   // split-K partials (max 8 splits of N<=768)

// ---------------- embedding + positional concat ----------------
__global__ void embed_kernel(const int* __restrict__ x, const int* __restrict__ ip,
                             const float* __restrict__ emb, const float* __restrict__ pe) {
    int n = blockIdx.x;
    int d = threadIdx.x;
    int tok = x[n];
    int i   = ip[0];
    g_h[n * DM + d]       = emb[tok * 256 + d];
    g_h[n * DM + 256 + d] = pe[i * 256 + d];
}

// ---------------- TF32 tensor-core GEMM core ----------------
// Block tile 128x64, BK=16, 256 threads = 8 warps (4m x 2n), warp tile 32x32.
// Fragment-major smem:
//  A: word = ((step*8 + blk16)*8 + g)*20 + j*4 + half + 2*kh   (2560 w/buf)
//  B: word = (step*64 + n)*10 + bswz(k&3, n)*2 + kh            (1280 w/buf)

__device__ __forceinline__ unsigned f2tf32(float f) {
    unsigned u;
    asm("cvt.rna.tf32.f32 %0, %1;" : "=r"(u) : "f"(f));
    return u;
}

__device__ __forceinline__ int bswz(int tg, int n) {
    return (tg + (n >> 2) + (n >> 4)) & 3;
}

template <int ACT>
__device__ __forceinline__ void gemm_body(
    const float* __restrict__ A, const float* __restrict__ B,
    const float* __restrict__ bias, float* __restrict__ C,
    int N, int K, int kStart, int kEnd, int m0, int n0)
{
    __shared__ __align__(16) unsigned As[2][2560];
    __shared__ __align__(16) unsigned Bs[2][1280];

    const int t    = threadIdx.x;
    const int warp = t >> 5;
    const int lane = t & 31;
    const int g    = lane >> 2;
    const int tg   = lane & 3;
    const int wm   = warp >> 1;       // 0..3 -> m offset 32*wm
    const int wn   = warp & 1;        // 0..1 -> n offset 32*wn

    // A loader: row ar (0..127), 8 consecutive k at ak8
    const int ar    = t >> 1;
    const int ak8   = (t & 1) * 8;
    const int ablk  = ar >> 4;
    const int ag    = ar & 7;
    const int ahalf = (ar >> 3) & 1;
    // B loader: k row bk (0..15), n quad bn4
    const int bk  = t >> 4;
    const int bn4 = (t & 15) * 4;

    const float* Ap = A + (size_t)(m0 + ar) * K + kStart + ak8;
    const float* Bp = B + (size_t)(kStart + bk) * N + n0 + bn4;

    const int nt = (kEnd - kStart) >> 4;   // BK = 16

    float c[2][4][4];
#pragma unroll
    for (int i = 0; i < 2; i++)
#pragma unroll
        for (int j = 0; j < 4; j++)
#pragma unroll
            for (int r = 0; r < 4; r++) c[i][j][r] = 0.f;

#define ST_A(buf, kkbase, v)                                                    \
    {                                                                           \
        const float va[4] = {(v).x, (v).y, (v).z, (v).w};                       \
        _Pragma("unroll")                                                       \
        for (int j = 0; j < 4; j++) {                                           \
            const int kq   = (kkbase) + j;                                      \
            const int step = kq >> 3;                                           \
            const int kh   = (kq >> 2) & 1;                                     \
            As[buf][((step * 8 + ablk) * 8 + ag) * 20 + (kq & 3) * 4 + ahalf + 2 * kh] \
                = f2tf32(va[j]);                                                \
        }                                                                       \
    }
#define ST_B(buf, kk, v)                                                        \
    {                                                                           \
        const float vb[4] = {(v).x, (v).y, (v).z, (v).w};                       \
        const int step = (kk) >> 3;                                             \
        const int tgk  = (kk) & 3;                                              \
        const int kh   = ((kk) >> 2) & 1;                                       \
        _Pragma("unroll")                                                       \
        for (int j = 0; j < 4; j++) {                                           \
            const int n = bn4 + j;                                              \
            Bs[buf][(step * 64 + n) * 10 + bswz(tgk, n) * 2 + kh] = f2tf32(vb[j]); \
        }                                                                       \
    }

    float4 aR0 = *(const float4*)Ap;
    float4 aR1 = *(const float4*)(Ap + 4);
    float4 bR0 = *(const float4*)Bp;

    ST_A(0, ak8, aR0);
    ST_A(0, ak8 + 4, aR1);
    ST_B(0, bk, bR0);
    __syncthreads();

    for (int kt = 0; kt < nt; kt++) {
        const int cur = kt & 1;
        if (kt + 1 < nt) {
            const float* Ap2 = Ap + (kt + 1) * 16;
            aR0 = *(const float4*)Ap2;
            aR1 = *(const float4*)(Ap2 + 4);
            bR0 = *(const float4*)(Bp + (size_t)(kt + 1) * 16 * N);
        }

#pragma unroll
        for (int step = 0; step < 2; step++) {
            uint4 af[2];
#pragma unroll
            for (int mt = 0; mt < 2; mt++)
                af[mt] = *(const uint4*)&As[cur][((step * 8 + wm * 2 + mt) * 8 + g) * 20 + tg * 4];
            uint2 bf[4];
#pragma unroll
            for (int ntl = 0; ntl < 4; ntl++) {
                const int col = wn * 32 + ntl * 8 + g;
                bf[ntl] = *(const uint2*)&Bs[cur][(step * 64 + col) * 10 + bswz(tg, col) * 2];
            }
#pragma unroll
            for (int mt = 0; mt < 2; mt++)
#pragma unroll
                for (int ntl = 0; ntl < 4; ntl++) {
                    asm volatile(
                        "mma.sync.aligned.m16n8k8.row.col.f32.tf32.tf32.f32 "
                        "{%0,%1,%2,%3}, {%4,%5,%6,%7}, {%8,%9}, {%0,%1,%2,%3};"
                        : "+f"(c[mt][ntl][0]), "+f"(c[mt][ntl][1]),
                          "+f"(c[mt][ntl][2]), "+f"(c[mt][ntl][3])
                        : "r"(af[mt].x), "r"(af[mt].y), "r"(af[mt].z), "r"(af[mt].w),
                          "r"(bf[ntl].x), "r"(bf[ntl].y));
                }
        }

        if (kt + 1 < nt) {
            const int nx = cur ^ 1;
            ST_A(nx, ak8, aR0);
            ST_A(nx, ak8 + 4, aR1);
            ST_B(nx, bk, bR0);
        }
        __syncthreads();
    }
#undef ST_A
#undef ST_B

    // epilogue
#pragma unroll
    for (int mt = 0; mt < 2; mt++) {
#pragma unroll
        for (int ntl = 0; ntl < 4; ntl++) {
#pragma unroll
            for (int half = 0; half < 2; half++) {
                const int row = m0 + wm * 32 + mt * 16 + g + half * 8;
                const int col = n0 + wn * 32 + ntl * 8 + tg * 2;
                float v0 = c[mt][ntl][half * 2 + 0];
                float v1 = c[mt][ntl][half * 2 + 1];
                if (bias) { v0 += bias[col]; v1 += bias[col + 1]; }
                if (ACT == 1) {
                    v0 = (v0 > 0.f) ? (v0 + 1.f) : __expf(v0);
                    v1 = (v1 > 0.f) ? (v1 + 1.f) : __expf(v1);
                }
                if (ACT == 2) { v0 = fmaxf(v0, 0.f); v1 = fmaxf(v1, 0.f); }
                float2 o = make_float2(v0, v1);
                *(float2*)&C[(size_t)row * N + col] = o;
            }
        }
    }
}

// Plain GEMM (full K); tile 128x64
template <int ACT>
__global__ __launch_bounds__(256, 2) void gemm_kernel(
    const float* __restrict__ A, const float* __restrict__ B,
    const float* __restrict__ bias, float* __restrict__ C, int N, int K)
{
    gemm_body<ACT>(A, B, bias, C, N, K, 0, K, blockIdx.y * 128, blockIdx.x * 64);
}

// Split-K GEMM: partials to Cp + z*NR*N
__global__ __launch_bounds__(256, 2) void gemm_splitk_kernel(
    const float* __restrict__ A, const float* __restrict__ B,
    float* __restrict__ Cp, int N, int K, int S)
{
    const int chunk = K / S;
    const int z = blockIdx.z;
    gemm_body<0>(A, B, nullptr, Cp + (size_t)z * NR * N,
                 N, K, z * chunk, (z + 1) * chunk, blockIdx.y * 128, blockIdx.x * 64);
}

// Fused QKV
__global__ __launch_bounds__(256, 2) void gemm_qkv_kernel(
    const float* __restrict__ h,
    const float* __restrict__ Wq, const float* __restrict__ Wk, const float* __restrict__ Wv,
    const float* __restrict__ bq, const float* __restrict__ bk, const float* __restrict__ bv,
    float* __restrict__ q, float* __restrict__ k, float* __restrict__ v, int l)
{
    const size_t w = (size_t)l * DM * DM;
    const int m0 = blockIdx.y * 128, n0 = blockIdx.x * 64;
    if (blockIdx.z == 0)
        gemm_body<1>(h, Wq + w, bq + l * DM, q, DM, DM, 0, DM, m0, n0);
    else if (blockIdx.z == 1)
        gemm_body<1>(h, Wk + w, bk + l * DM, k, DM, DM, 0, DM, m0, n0);
    else
        gemm_body<0>(h, Wv + w, bv + l * DM, v, DM, DM, 0, DM, m0, n0);
}

// ---------------- split-K reduce + bias (for pred head) ----------------
__global__ void reduce_bias_kernel(const float* __restrict__ part, int P,
                                   const float* __restrict__ bias,
                                   float* __restrict__ outp, int N)
{
    const int n = blockIdx.x;
    for (int c = threadIdx.x; c < N; c += blockDim.x) {
        float v = bias[c];
        for (int p = 0; p < P; p++)
            v += part[(size_t)p * NR * N + (size_t)n * N + c];
        outp[(size_t)n * N + c] = v;
    }
}

// ---------------- linear-attention state update + readout ----------------
__global__ void attn_kernel(const float* __restrict__ Q, const float* __restrict__ Kmat,
                            const float* __restrict__ V,
                            const float* __restrict__ Si, const float* __restrict__ Zi,
                            float* __restrict__ S_out, float* __restrict__ Z_out,
                            float* __restrict__ attn)
{
    const int n = blockIdx.x;
    const int h = blockIdx.y;
    const int m = threadIdx.x;

    __shared__ float qs[HE], ks[HE], red[HE];

    const int baseqk = n * DM + h * HE;
    qs[m] = Q[baseqk + m];
    ks[m] = Kmat[baseqk + m];
    const float vm = V[baseqk + m];

    const size_t zbase = ((size_t)n * NH + h) * HE;
    const float z = Zi[zbase + m] + ks[m];
    Z_out[zbase + m] = z;

    red[m] = qs[m] * z;
    __syncthreads();
#pragma unroll
    for (int s = 32; s > 0; s >>= 1) {
        if (m < s) red[m] += red[m + s];
        __syncthreads();
    }
    const float den = red[0] + 1e-6f;

    const size_t sbase = ((size_t)n * NH + h) * HE * HE;
    float num = 0.f;
#pragma unroll 8
    for (int e = 0; e < HE; e++) {
        float s = Si[sbase + (size_t)e * HE + m] + ks[e] * vm;
        S_out[sbase + (size_t)e * HE + m] = s;
        num = fmaf(qs[e], s, num);
    }
    attn[baseqk + m] = num / den;
}

// ---------------- residual + split-K reduce + bias + LayerNorm -----------
__global__ void add_ln_kernel(float* __restrict__ hbuf, const float* __restrict__ part,
                              int P, const float* __restrict__ bias,
                              const float* __restrict__ g, const float* __restrict__ b)
{
    const int n = blockIdx.x;
    const int t = threadIdx.x;
    __shared__ float red[256];
    __shared__ float s_mean, s_rstd;

    float v0 = hbuf[n * DM + t];
    float v1 = hbuf[n * DM + 256 + t];
    for (int p = 0; p < P; p++) {
        v0 += part[(size_t)p * NR * DM + n * DM + t];
        v1 += part[(size_t)p * NR * DM + n * DM + 256 + t];
    }
    if (bias) { v0 += bias[t]; v1 += bias[256 + t]; }

    red[t] = v0 + v1;
    __syncthreads();
#pragma unroll
    for (int s = 128; s > 0; s >>= 1) {
        if (t < s) red[t] += red[t + s];
        __syncthreads();
    }
    if (t == 0) s_mean = red[0] * (1.f / DM);
    __syncthreads();
    const float mean = s_mean;

    float d0 = v0 - mean, d1 = v1 - mean;
    red[t] = d0 * d0 + d1 * d1;
    __syncthreads();
#pragma unroll
    for (int s = 128; s > 0; s >>= 1) {
        if (t < s) red[t] += red[t + s];
        __syncthreads();
    }
    if (t == 0) s_rstd = rsqrtf(red[0] * (1.f / DM) + 1e-5f);
    __syncthreads();
    const float rstd = s_rstd;

    hbuf[n * DM + t]       = d0 * rstd * g[t]       + b[t];
    hbuf[n * DM + 256 + t] = d1 * rstd * g[256 + t] + b[256 + t];
}

// ---------------- host-side launch ----------------
extern "C" void kernel_launch(void* const* d_in, const int* in_sizes, int n_in,
                              void* d_out, int out_size)
{
    const int*   x      = (const int*)  d_in[0];
    const int*   ip     = (const int*)  d_in[1];
    const float* emb    = (const float*)d_in[2];
    const float* pe     = (const float*)d_in[3];
    const float* Wq     = (const float*)d_in[4];
    const float* bq     = (const float*)d_in[5];
    const float* Wk     = (const float*)d_in[6];
    const float* bk     = (const float*)d_in[7];
    const float* Wv     = (const float*)d_in[8];
    const float* bv     = (const float*)d_in[9];
    const float* Wo     = (const float*)d_in[10];
    const float* bo     = (const float*)d_in[11];
    const float* ln1_g  = (const float*)d_in[12];
    const float* ln1_b  = (const float*)d_in[13];
    const float* lin1_w = (const float*)d_in[14];
    const float* lin1_b = (const float*)d_in[15];
    const float* lin2_w = (const float*)d_in[16];
    const float* lin2_b = (const float*)d_in[17];
    const float* ln2_g  = (const float*)d_in[18];
    const float* ln2_b  = (const float*)d_in[19];
    const float* lnf_g  = (const float*)d_in[20];
    const float* lnf_b  = (const float*)d_in[21];
    const float* pred_w = (const float*)d_in[22];
    const float* pred_b = (const float*)d_in[23];
    const float* Si     = (const float*)d_in[24];
    const float* Zi     = (const float*)d_in[25];

    float* out = (float*)d_out;
    float* out_yhat = out;
    float* out_S    = out + (size_t)NR * MIX3;
    float* out_Z    = out_S + (size_t)NL * NR * NH * HE * HE;

    float *h, *q, *k, *v, *attn, *ffn, *part;
    cudaGetSymbolAddress((void**)&h,    g_h);
    cudaGetSymbolAddress((void**)&q,    g_q);
    cudaGetSymbolAddress((void**)&k,    g_k);
    cudaGetSymbolAddress((void**)&v,    g_v);
    cudaGetSymbolAddress((void**)&attn, g_attn);
    cudaGetSymbolAddress((void**)&ffn,  g_ffn);
    cudaGetSymbolAddress((void**)&part, g_part);

    embed_kernel<<<NR, 256>>>(x, ip, emb, pe);

    const dim3 gQKV(DM / 64, NR / 128, 3);     // 8x4x3 = 96 blocks
    const dim3 gWo(DM / 64, NR / 128, 4);      // split-K 4 -> 128 blocks
    const dim3 gF1(FF / 64, NR / 128);         // 32x4 = 128 blocks
    const dim3 gF2(DM / 64, NR / 128, 8);      // split-K 8 -> 256 blocks
    const dim3 gPred(MIX3 / 64, NR / 128, 4);  // split-K 4 -> 192 blocks
    const dim3 gAttn(NR, NH);

    const size_t ssz = (size_t)NR * NH * HE * HE;
    const size_t zsz = (size_t)NR * NH * HE;

    for (int l = 0; l < NL; l++) {
        gemm_qkv_kernel<<<gQKV, 256>>>(h, Wq, Wk, Wv, bq, bk, bv, q, k, v, l);

        attn_kernel<<<gAttn, HE>>>(q, k, v, Si + l * ssz, Zi + l * zsz,
                                   out_S + l * ssz, out_Z + l * zsz, attn);

        gemm_splitk_kernel<<<gWo, 256>>>(attn, Wo + (size_t)l * DM * DM, part, DM, DM, 4);
        add_ln_kernel<<<NR, 256>>>(h, part, 4, bo + l * DM, ln1_g + l * DM, ln1_b + l * DM);

        gemm_kernel<2><<<gF1, 256>>>(h, lin1_w + (size_t)l * DM * FF, lin1_b + l * FF,
                                     ffn, FF, DM);
        gemm_splitk_kernel<<<gF2, 256>>>(ffn, lin2_w + (size_t)l * FF * DM, part, DM, FF, 8);
        add_ln_kernel<<<NR, 256>>>(h, part, 8, lin2_b + l * DM, ln2_g + l * DM, ln2_b + l * DM);
    }

    add_ln_kernel<<<NR, 256>>>(h, (const float*)nullptr, 0, (const float*)nullptr, lnf_g, lnf_b);
    gemm_splitk_kernel<<<gPred, 256>>>(h, pred_w, part, MIX3, DM, 4);
    reduce_bias_kernel<<<NR, 256>>>(part, 4, pred_b, out_yhat, MIX3);
}